// round 13
// baseline (speedup 1.0000x reference)
#include <cuda_runtime.h>

// TT embedding lookup, GB300 sm_103a — v6: r0-slice-parallel dedup.
// core1 read EXACTLY ONCE chip-wide (110 MB): each (bucket, r0-slice-of-16)
// is one CTA; warps split q1 (perfect balance); samples chunked by 4 in regs.
// Partials to __device__ scratch, fixed-order reduce kernel => deterministic.
//
// out[q0,q1,q2] = sum_{r0,r1} A[q0*128+r0] * Bm[r0*512+q1*128+r1] * C[r1*2+q2]

#define NTAB   2
#define BATCH  1024
#define PDIM   216
#define P12    46656
#define NBKT   (NTAB * PDIM)      // 432
#define NSLICE 8
#define SLICE_R 16                // r0 rows per slice
#define NTHR   128

__device__ int   g_idx_is64;
__device__ int   g_cnt[NBKT];
__device__ int   g_list[NBKT * BATCH];            // worst case: all in one bucket
__device__ float g_part[NTAB * BATCH * NSLICE * 16];   // 1 MB partials

// ---------------------------------------------------------------- kernels --
__global__ void zero_cnt_kernel()
{
    const int i = threadIdx.x;
    if (i < NBKT) g_cnt[i] = 0;
}

__global__ void probe_dtype_kernel(const int* __restrict__ raw)
{
    int is64 = 1;
#pragma unroll
    for (int k = 0; k < 32; k++)
        if (raw[2 * k + 1] != 0) is64 = 0;
    g_idx_is64 = is64;
}

__global__ void build_lists_kernel(const void* __restrict__ lS_i_raw)
{
    const int t = blockIdx.x;
    const int j = threadIdx.x;
    const int pos = t * BATCH + j;
    const int* raw = (const int*)lS_i_raw;
    int v = g_idx_is64 ? raw[2 * pos] : raw[pos];   // idx < 1e7 < 2^31
    v = max(v, 0);
    int i0  = v / P12;
    int rem = v - i0 * P12;
    int i1  = rem / PDIM;
    int i2  = rem - i1 * PDIM;
    i0 = min(i0, PDIM - 1);
    const int bkt = t * PDIM + i1;
    const int p = atomicAdd(&g_cnt[bkt], 1);
    g_list[bkt * BATCH + p] = j | (i0 << 10) | (i2 << 18);
}

// ---- packed f32x2 helpers ------------------------------------------------
typedef unsigned long long u64t;

__device__ __forceinline__ u64t pack2(float lo, float hi) {
    u64t r; asm("mov.b64 %0,{%1,%2};" : "=l"(r) : "f"(lo), "f"(hi)); return r;
}
__device__ __forceinline__ u64t dup2(float x) { return pack2(x, x); }
__device__ __forceinline__ u64t mul2(u64t a, u64t b) {
    u64t d; asm("mul.rn.f32x2 %0,%1,%2;" : "=l"(d) : "l"(a), "l"(b)); return d;
}
__device__ __forceinline__ u64t fma2(u64t a, u64t b, u64t c) {
    u64t d; asm("fma.rn.f32x2 %0,%1,%2,%3;" : "=l"(d) : "l"(a), "l"(b), "l"(c)); return d;
}
__device__ __forceinline__ u64t add2(u64t a, u64t b) {
    u64t d; asm("add.rn.f32x2 %0,%1,%2;" : "=l"(d) : "l"(a), "l"(b)); return d;
}

// ---- compute: one CTA per (bucket, slice) --------------------------------
__global__ __launch_bounds__(NTHR, 6)
void tt_slice_kernel(const float* __restrict__ core0,
                     const float* __restrict__ core1,
                     const float* __restrict__ core2)
{
    const int tb   = blockIdx.x;              // bucket
    const int z    = blockIdx.y;              // slice
    const int t    = tb / PDIM;
    const int tid  = threadIdx.x;
    const int warp = tid >> 5;                // = q1
    const int lane = tid & 31;                // owns r1 in [4*lane, 4*lane+4)

    const int S = g_cnt[tb];
    if (S == 0) return;

    __shared__ float4 sB[SLICE_R * 128];      // 32 KB slice

    // ---- stream slice into smem (read ONCE chip-wide) ---------------------
    {
        const float4* src = (const float4*)core1 + (size_t)tb * 16384
                          + (size_t)z * (SLICE_R * 128);
#pragma unroll
        for (int u = 0; u < (SLICE_R * 128) / NTHR; u++) {
            const int idx = u * NTHR + tid;
            unsigned d = (unsigned)__cvta_generic_to_shared(&sB[idx]);
            asm volatile("cp.async.cg.shared.global [%0], [%1], 16;"
                         :: "r"(d), "l"(src + idx) : "memory");
        }
        asm volatile("cp.async.commit_group;" ::: "memory");
    }

    const int* list = g_list + tb * BATCH;
    bool waited = false;

    for (int base = 0; base < S; base += 4) {
        const int nsam = min(4, S - base);

        // ---- per-chunk sample data (registers) ----------------------------
        int  item[4];
        u64t cs[4][4];
        float av[4];                // lane<16: A[q0=0][z*16+lane]; else q0=1
#pragma unroll
        for (int s = 0; s < 4; s++) {
            item[s] = 0; av[s] = 0.f;
            cs[s][0] = cs[s][1] = cs[s][2] = cs[s][3] = 0ULL;
        }
        const int aoff = ((lane >> 4) << 7) + z * SLICE_R + (lane & 15);
#pragma unroll
        for (int s = 0; s < 4; s++) {
            if (s < nsam) {
                const int it = list[base + s];
                item[s] = it;
                const int i0 = (it >> 10) & 255;
                const int i2 = (it >> 18) & 255;
                av[s] = core0[((size_t)t * PDIM + i0) * 256 + aoff];
                const float4* Crow =
                    (const float4*)(core2 + ((size_t)t * PDIM + i2) * 256);
                const float4 c0 = Crow[lane * 2], c1 = Crow[lane * 2 + 1];
                cs[s][0] = pack2(c0.x, c0.y); cs[s][1] = pack2(c0.z, c0.w);
                cs[s][2] = pack2(c1.x, c1.y); cs[s][3] = pack2(c1.z, c1.w);
            }
        }

        u64t acc[4][2];
#pragma unroll
        for (int s = 0; s < 4; s++) { acc[s][0] = 0ULL; acc[s][1] = 0ULL; }

        if (!waited) {   // overlap C/A gather latency with the slice copy
            asm volatile("cp.async.wait_group 0;" ::: "memory");
            __syncthreads();
            waited = true;
        }

        // ---- contraction: warp covers q1=warp, lane covers 4 r1 -----------
#pragma unroll
        for (int r = 0; r < SLICE_R; r++) {
            const float4 bv = sB[r * 128 + warp * 32 + lane];  // conflict-free
            const u64t bx = dup2(bv.x), by = dup2(bv.y);
            const u64t bz = dup2(bv.z), bw = dup2(bv.w);
#pragma unroll
            for (int s = 0; s < 4; s++) {
                const float a0 = __shfl_sync(0xffffffffu, av[s], r);
                const float a1 = __shfl_sync(0xffffffffu, av[s], 16 + r);
                u64t tp = mul2(bx, cs[s][0]);
                tp = fma2(by, cs[s][1], tp);
                tp = fma2(bz, cs[s][2], tp);
                tp = fma2(bw, cs[s][3], tp);
                acc[s][0] = fma2(dup2(a0), tp, acc[s][0]);
                acc[s][1] = fma2(dup2(a1), tp, acc[s][1]);
            }
        }

        // ---- butterfly over lanes completes the r1 sum --------------------
#pragma unroll
        for (int off = 16; off; off >>= 1)
#pragma unroll
            for (int s = 0; s < 4; s++) {
                acc[s][0] = add2(acc[s][0], __shfl_xor_sync(0xffffffffu, acc[s][0], off));
                acc[s][1] = add2(acc[s][1], __shfl_xor_sync(0xffffffffu, acc[s][1], off));
            }

        if (lane == 0) {
#pragma unroll
            for (int s = 0; s < 4; s++) {
                if (s < nsam) {
                    const int b = item[s] & 1023;
                    float* pp = g_part + (((size_t)(t * BATCH + b)) * NSLICE + z) * 16;
                    // element (q0,q1,q2) at q0*8 + q1*2 + q2; packed pair = (q2=0,q2=1)
                    *(u64t*)(pp + warp * 2)     = acc[s][0];
                    *(u64t*)(pp + 8 + warp * 2) = acc[s][1];
                }
            }
        }
    }
}

// ---- reduce: fixed-order sum over 8 slices (deterministic) ---------------
__global__ void reduce_kernel(float* __restrict__ out)
{
    const int gid = blockIdx.x * blockDim.x + threadIdx.x;   // 8192 threads
    const int sample = gid >> 2;
    const int k4     = gid & 3;
    const float4* pp = (const float4*)(g_part + ((size_t)sample * NSLICE) * 16) + k4;
    float4 sum = make_float4(0.f, 0.f, 0.f, 0.f);
#pragma unroll
    for (int zz = 0; zz < NSLICE; zz++) {
        const float4 v = pp[zz * 4];
        sum.x += v.x; sum.y += v.y; sum.z += v.z; sum.w += v.w;
    }
    ((float4*)out)[sample * 4 + k4] = sum;
}

extern "C" void kernel_launch(void* const* d_in, const int* in_sizes, int n_in,
                              void* d_out, int out_size)
{
    const void*  lS_i  = d_in[0];
    const float* core0 = (const float*)d_in[1];
    const float* core1 = (const float*)d_in[2];
    const float* core2 = (const float*)d_in[3];
    float*       out   = (float*)d_out;

    zero_cnt_kernel<<<1, 512>>>();
    probe_dtype_kernel<<<1, 1>>>((const int*)lS_i);
    build_lists_kernel<<<NTAB, BATCH>>>(lS_i);
    tt_slice_kernel<<<dim3(NBKT, NSLICE), NTHR>>>(core0, core1, core2);
    reduce_kernel<<<32, 256>>>(out);
}

// round 14
// speedup vs baseline: 1.0891x; 1.0891x over previous
#include <cuda_runtime.h>

// TT embedding lookup, GB300 sm_103a — v7: r0-slice-parallel dedup, fused.
// vs v6 (49.7us = 38.8 slice + ~11 launch overhead):
//  * 2 launches instead of 5 (init fuses zero+probe+build; reduce folded into
//    slice kernel via threadfence+atomic arrival counter, fixed-order sum)
//  * nsam-specialized inner loops kill the ~31% padded-slot issue waste
//  * A chunk values staged to smem (LDS broadcast) instead of 128 SHFLs
//
// out[q0,q1,q2] = sum_{r0,r1} A[q0*128+r0] * Bm[r0*512+q1*128+r1] * C[r1*2+q2]

#define NTAB    2
#define BATCH   1024
#define PDIM    216
#define P12     46656
#define NBKT    (NTAB * PDIM)     // 432
#define NSLICE  8
#define SLICE_R 16                // r0 rows per slice
#define NTHR    128

__device__ int   g_idx_is64;
__device__ int   g_cnt[NBKT];
__device__ int   g_done[NBKT];
__device__ int   g_list[NBKT * BATCH];
__device__ float g_part[NTAB * BATCH * NSLICE * 16];

// ---- packed f32x2 helpers ------------------------------------------------
typedef unsigned long long u64t;

__device__ __forceinline__ u64t pack2(float lo, float hi) {
    u64t r; asm("mov.b64 %0,{%1,%2};" : "=l"(r) : "f"(lo), "f"(hi)); return r;
}
__device__ __forceinline__ u64t dup2(float x) { return pack2(x, x); }
__device__ __forceinline__ u64t mul2(u64t a, u64t b) {
    u64t d; asm("mul.rn.f32x2 %0,%1,%2;" : "=l"(d) : "l"(a), "l"(b)); return d;
}
__device__ __forceinline__ u64t fma2(u64t a, u64t b, u64t c) {
    u64t d; asm("fma.rn.f32x2 %0,%1,%2,%3;" : "=l"(d) : "l"(a), "l"(b), "l"(c)); return d;
}
__device__ __forceinline__ u64t add2(u64t a, u64t b) {
    u64t d; asm("add.rn.f32x2 %0,%1,%2;" : "=l"(d) : "l"(a), "l"(b)); return d;
}

// ---- init: zero counters + dtype probe + bucket lists (ONE CTA) ----------
__global__ void init_kernel(const int* __restrict__ raw)
{
    const int tid = threadIdx.x;          // 1024 threads
    __shared__ int s64;
    if (tid < NBKT) { g_cnt[tid] = 0; g_done[tid] = 0; }
    if (tid == 0) {
        int is64 = 1;
#pragma unroll
        for (int k = 0; k < 32; k++)
            if (raw[2 * k + 1] != 0) is64 = 0;
        g_idx_is64 = is64;
        s64 = is64;
    }
    __syncthreads();
    const int is64 = s64;
    for (int pos = tid; pos < NTAB * BATCH; pos += 1024) {
        int v = is64 ? raw[2 * pos] : raw[pos];   // idx < 1e7 < 2^31
        v = max(v, 0);
        int i0  = v / P12;
        int rem = v - i0 * P12;
        int i1  = rem / PDIM;
        int i2  = rem - i1 * PDIM;
        i0 = min(i0, PDIM - 1);
        const int t = pos >> 10, j = pos & 1023;
        const int bkt = t * PDIM + i1;
        const int p = atomicAdd(&g_cnt[bkt], 1);
        g_list[bkt * BATCH + p] = j | (i0 << 10) | (i2 << 18);
    }
}

// ---- chunk body, specialized on live sample count NS ----------------------
template<int NS>
__device__ __forceinline__ void chunk_body(
    const float4* __restrict__ sB, const float (*sAv)[32],
    const float* __restrict__ core2t, const int* __restrict__ list,
    int base, int t, int z, int warp, int lane)
{
    int  item[NS];
    u64t cs[NS][4];
#pragma unroll
    for (int s = 0; s < NS; s++) {
        const int it = list[base + s];
        item[s] = it;
        const int i2 = (it >> 18) & 255;
        const float4* Crow = (const float4*)(core2t + (size_t)i2 * 256);
        const float4 c0 = Crow[lane * 2], c1 = Crow[lane * 2 + 1];
        cs[s][0] = pack2(c0.x, c0.y); cs[s][1] = pack2(c0.z, c0.w);
        cs[s][2] = pack2(c1.x, c1.y); cs[s][3] = pack2(c1.z, c1.w);
    }

    u64t acc[NS][2];
#pragma unroll
    for (int s = 0; s < NS; s++) { acc[s][0] = 0ULL; acc[s][1] = 0ULL; }

#pragma unroll
    for (int r = 0; r < SLICE_R; r++) {
        const float4 bv = sB[r * 128 + warp * 32 + lane];   // conflict-free
        const u64t bx = dup2(bv.x), by = dup2(bv.y);
        const u64t bz = dup2(bv.z), bw = dup2(bv.w);
#pragma unroll
        for (int s = 0; s < NS; s++) {
            const float a0 = sAv[s][r];          // LDS broadcast
            const float a1 = sAv[s][16 + r];
            u64t tp = mul2(bx, cs[s][0]);
            tp = fma2(by, cs[s][1], tp);
            tp = fma2(bz, cs[s][2], tp);
            tp = fma2(bw, cs[s][3], tp);
            acc[s][0] = fma2(dup2(a0), tp, acc[s][0]);
            acc[s][1] = fma2(dup2(a1), tp, acc[s][1]);
        }
    }

#pragma unroll
    for (int off = 16; off; off >>= 1)
#pragma unroll
        for (int s = 0; s < NS; s++) {
            acc[s][0] = add2(acc[s][0], __shfl_xor_sync(0xffffffffu, acc[s][0], off));
            acc[s][1] = add2(acc[s][1], __shfl_xor_sync(0xffffffffu, acc[s][1], off));
        }

    if (lane == 0) {
#pragma unroll
        for (int s = 0; s < NS; s++) {
            const int b = item[s] & 1023;
            float* pp = g_part + (((size_t)(t * BATCH + b)) * NSLICE + z) * 16;
            *(u64t*)(pp + warp * 2)     = acc[s][0];   // q0=0, q1=warp
            *(u64t*)(pp + 8 + warp * 2) = acc[s][1];   // q0=1
        }
    }
}

// ---- compute: one CTA per (bucket, slice); last CTA of bucket reduces ----
__global__ __launch_bounds__(NTHR, 6)
void tt_slice_kernel(const float* __restrict__ core0,
                     const float* __restrict__ core1,
                     const float* __restrict__ core2,
                     float* __restrict__ out)
{
    const int tb   = blockIdx.x;
    const int z    = blockIdx.y;
    const int t    = tb / PDIM;
    const int tid  = threadIdx.x;
    const int warp = tid >> 5;               // = q1
    const int lane = tid & 31;               // owns r1 in [4*lane, 4*lane+4)

    const int S = g_cnt[tb];
    if (S == 0) return;

    __shared__ float4 sB[SLICE_R * 128];     // 32 KB slice
    __shared__ float  sAv[4][32];            // staged A values per chunk
    __shared__ int    sLast;

    // stream slice into smem (read ONCE chip-wide)
    {
        const float4* src = (const float4*)core1 + (size_t)tb * 16384
                          + (size_t)z * (SLICE_R * 128);
#pragma unroll
        for (int u = 0; u < (SLICE_R * 128) / NTHR; u++) {
            const int idx = u * NTHR + tid;
            unsigned d = (unsigned)__cvta_generic_to_shared(&sB[idx]);
            asm volatile("cp.async.cg.shared.global [%0], [%1], 16;"
                         :: "r"(d), "l"(src + idx) : "memory");
        }
        asm volatile("cp.async.commit_group;" ::: "memory");
    }

    const int*   list   = g_list + tb * BATCH;
    const float* core2t = core2 + (size_t)t * PDIM * 256;

    for (int base = 0; base < S; base += 4) {
        const int nsam = min(4, S - base);

        // stage A: warp w loads sample (base+w)'s 32 slice values
        if (warp < nsam) {
            const int it = list[base + warp];
            const int i0 = (it >> 10) & 255;
            const int aoff = ((lane >> 4) << 7) + z * SLICE_R + (lane & 15);
            sAv[warp][lane] = core0[((size_t)t * PDIM + i0) * 256 + aoff];
        }
        if (base == 0)
            asm volatile("cp.async.wait_group 0;" ::: "memory");
        __syncthreads();                     // sAv (and sB on first pass) ready

        switch (nsam) {
            case 4: chunk_body<4>(sB, sAv, core2t, list, base, t, z, warp, lane); break;
            case 3: chunk_body<3>(sB, sAv, core2t, list, base, t, z, warp, lane); break;
            case 2: chunk_body<2>(sB, sAv, core2t, list, base, t, z, warp, lane); break;
            default: chunk_body<1>(sB, sAv, core2t, list, base, t, z, warp, lane); break;
        }
        __syncthreads();                     // before next chunk overwrites sAv
    }

    // ---- fused reduce: 8th-arriving CTA of this bucket sums the slices ----
    __threadfence();
    if (tid == 0)
        sLast = (atomicAdd(&g_done[tb], 1) == NSLICE - 1) ? 1 : 0;
    __syncthreads();
    if (sLast) {
        for (int w = tid; w < S * 4; w += NTHR) {
            const int s  = w >> 2;
            const int k4 = w & 3;
            const int b  = list[s] & 1023;
            const float4* pp = (const float4*)
                (g_part + ((size_t)(t * BATCH + b)) * NSLICE * 16) + k4;
            float4 sum = make_float4(0.f, 0.f, 0.f, 0.f);
#pragma unroll
            for (int zz = 0; zz < NSLICE; zz++) {
                const float4 v = __ldcg(pp + zz * 4);   // L2-fresh
                sum.x += v.x; sum.y += v.y; sum.z += v.z; sum.w += v.w;
            }
            ((float4*)out)[((size_t)(t * BATCH + b)) * 4 + k4] = sum;
        }
    }
}

extern "C" void kernel_launch(void* const* d_in, const int* in_sizes, int n_in,
                              void* d_out, int out_size)
{
    const void*  lS_i  = d_in[0];
    const float* core0 = (const float*)d_in[1];
    const float* core1 = (const float*)d_in[2];
    const float* core2 = (const float*)d_in[3];
    float*       out   = (float*)d_out;

    init_kernel<<<1, 1024>>>((const int*)lS_i);
    tt_slice_kernel<<<dim3(NBKT, NSLICE), NTHR>>>(core0, core1, core2, out);
}